// round 1
// baseline (speedup 1.0000x reference)
#include <cuda_runtime.h>

// Problem dims
constexpr int S  = 24;
constexpr int Bn = 256;
constexpr int Dm = 1024;
constexpr int Hn = 16;
constexpr int Ln = 12;
constexpr int Vn = 32000;
constexpr int DH = 64;
constexpr int Mr = S * Bn;  // 6144 rows

// Scratch buffers (allowed: __device__ globals, no allocation)
__device__ float g_x[(size_t)Mr * Dm];
__device__ float g_q[(size_t)Mr * Dm];
__device__ float g_k[(size_t)Mr * Dm];
__device__ float g_v[(size_t)Mr * Dm];

// ---------------------------------------------------------------------------
// Embedding: x[s*B+b, :] = token_embed[inputs[s,b], :] + pe[s, 0, :]
// ---------------------------------------------------------------------------
__global__ void embed_kernel(const int* __restrict__ inputs,
                             const float* __restrict__ tok,
                             const float* __restrict__ pe) {
    int row = blockIdx.x;            // s*B + b
    int s = row / Bn;
    int t = inputs[row];
    const float4* te = reinterpret_cast<const float4*>(tok + (size_t)t * Dm);
    const float4* pp = reinterpret_cast<const float4*>(pe + (size_t)s * Dm);
    float4* xo = reinterpret_cast<float4*>(g_x + (size_t)row * Dm);
    float4 a = te[threadIdx.x];
    float4 b = pp[threadIdx.x];
    xo[threadIdx.x] = make_float4(a.x + b.x, a.y + b.y, a.z + b.z, a.w + b.w);
}

// ---------------------------------------------------------------------------
// SGEMM NT: C[m,n] = sum_k A[m,k] * W[n,k] + bias[n]
// Tile 128x128x16, 256 threads, 8x8 per thread, float4 everywhere.
// K = 1024 fixed. All tile dims divide exactly (no bounds checks).
// ---------------------------------------------------------------------------
__device__ __forceinline__ void gemm_body(
    const float* __restrict__ A, const float* __restrict__ W,
    const float* __restrict__ bias, float* __restrict__ C,
    int ldC, int mTile, int nTile)
{
    constexpr int K = Dm;
    __shared__ float As[16][132];   // [k][m], padded: stride 132 keeps 16B align
    __shared__ float Ws[16][132];   // [k][n]

    const int tid = threadIdx.x;
    const int tx = tid & 15;        // n direction (16 threads * 8 = 128)
    const int ty = tid >> 4;        // m direction
    const int m0 = mTile * 128;
    const int n0 = nTile * 128;

    // Global load mapping: 128 rows x 16 cols = 512 float4; 2 per thread
    const int lrow = tid >> 2;          // 0..63
    const int lc4  = (tid & 3) << 2;    // 0,4,8,12

    const float* Ap0 = A + (size_t)(m0 + lrow) * K + lc4;
    const float* Ap1 = A + (size_t)(m0 + 64 + lrow) * K + lc4;
    const float* Wp0 = W + (size_t)(n0 + lrow) * K + lc4;
    const float* Wp1 = W + (size_t)(n0 + 64 + lrow) * K + lc4;

    float acc[8][8];
#pragma unroll
    for (int i = 0; i < 8; i++)
#pragma unroll
        for (int j = 0; j < 8; j++) acc[i][j] = 0.f;

    for (int k0 = 0; k0 < K; k0 += 16) {
        float4 a0 = *reinterpret_cast<const float4*>(Ap0 + k0);
        float4 a1 = *reinterpret_cast<const float4*>(Ap1 + k0);
        float4 w0 = *reinterpret_cast<const float4*>(Wp0 + k0);
        float4 w1 = *reinterpret_cast<const float4*>(Wp1 + k0);
        __syncthreads();   // previous compute done before overwriting smem
        As[lc4 + 0][lrow]      = a0.x;
        As[lc4 + 1][lrow]      = a0.y;
        As[lc4 + 2][lrow]      = a0.z;
        As[lc4 + 3][lrow]      = a0.w;
        As[lc4 + 0][64 + lrow] = a1.x;
        As[lc4 + 1][64 + lrow] = a1.y;
        As[lc4 + 2][64 + lrow] = a1.z;
        As[lc4 + 3][64 + lrow] = a1.w;
        Ws[lc4 + 0][lrow]      = w0.x;
        Ws[lc4 + 1][lrow]      = w0.y;
        Ws[lc4 + 2][lrow]      = w0.z;
        Ws[lc4 + 3][lrow]      = w0.w;
        Ws[lc4 + 0][64 + lrow] = w1.x;
        Ws[lc4 + 1][64 + lrow] = w1.y;
        Ws[lc4 + 2][64 + lrow] = w1.z;
        Ws[lc4 + 3][64 + lrow] = w1.w;
        __syncthreads();
#pragma unroll
        for (int kk = 0; kk < 16; kk++) {
            float4 av0 = *reinterpret_cast<const float4*>(&As[kk][ty * 8]);
            float4 av1 = *reinterpret_cast<const float4*>(&As[kk][ty * 8 + 4]);
            float4 wv0 = *reinterpret_cast<const float4*>(&Ws[kk][tx * 8]);
            float4 wv1 = *reinterpret_cast<const float4*>(&Ws[kk][tx * 8 + 4]);
            float ar[8] = {av0.x, av0.y, av0.z, av0.w, av1.x, av1.y, av1.z, av1.w};
            float wr[8] = {wv0.x, wv0.y, wv0.z, wv0.w, wv1.x, wv1.y, wv1.z, wv1.w};
#pragma unroll
            for (int i = 0; i < 8; i++)
#pragma unroll
                for (int j = 0; j < 8; j++)
                    acc[i][j] = fmaf(ar[i], wr[j], acc[i][j]);
        }
    }

    float bj[8];
#pragma unroll
    for (int j = 0; j < 8; j++) bj[j] = bias[n0 + tx * 8 + j];
#pragma unroll
    for (int i = 0; i < 8; i++) {
        size_t r = (size_t)(m0 + ty * 8 + i) * ldC + n0 + tx * 8;
        float4 o0 = make_float4(acc[i][0] + bj[0], acc[i][1] + bj[1],
                                acc[i][2] + bj[2], acc[i][3] + bj[3]);
        float4 o1 = make_float4(acc[i][4] + bj[4], acc[i][5] + bj[5],
                                acc[i][6] + bj[6], acc[i][7] + bj[7]);
        *reinterpret_cast<float4*>(C + r)     = o0;
        *reinterpret_cast<float4*>(C + r + 4) = o1;
    }
}

// Fused QKV projection: grid (48, 24); blockIdx.y selects matrix (0..2) & n-tile
__global__ void __launch_bounds__(256) qkv_kernel(
    const float* __restrict__ qw, const float* __restrict__ kw,
    const float* __restrict__ vw, const float* __restrict__ qb,
    const float* __restrict__ kb, const float* __restrict__ vb)
{
    int mat = blockIdx.y >> 3;        // 0..2 (1024/128 = 8 n-tiles per matrix)
    int nT  = blockIdx.y & 7;
    const float* W    = (mat == 0) ? qw : (mat == 1) ? kw : vw;
    const float* bias = (mat == 0) ? qb : (mat == 1) ? kb : vb;
    float* C          = (mat == 0) ? g_q : (mat == 1) ? g_k : g_v;
    gemm_body(g_x, W, bias, C, Dm, blockIdx.x, nT);
}

// Final logits GEMM: grid (48, 250)
__global__ void __launch_bounds__(256) out_kernel(
    const float* __restrict__ ow, const float* __restrict__ ob,
    float* __restrict__ out)
{
    gemm_body(g_x, ow, ob, out, Vn, blockIdx.x, blockIdx.y);
}

// ---------------------------------------------------------------------------
// Attention per (b,h): scores->softmax->AV->residual, fused in one block.
// ---------------------------------------------------------------------------
__global__ void __launch_bounds__(256) attn_kernel() {
    int bh = blockIdx.x;
    int b = bh >> 4;     // / H
    int h = bh & 15;     // % H
    __shared__ float qs[S][DH + 1];
    __shared__ float ks[S][DH + 1];
    __shared__ float vs[S][DH + 1];
    __shared__ float sc[S][S];
    int tid = threadIdx.x;

    for (int p = tid; p < S * DH; p += 256) {
        int s = p >> 6;
        int d = p & 63;
        size_t g = (size_t)(s * Bn + b) * Dm + h * DH + d;
        qs[s][d] = g_q[g];
        ks[s][d] = g_k[g];
        vs[s][d] = g_v[g];
    }
    __syncthreads();

    constexpr float scale = 0.03125f;   // 1/sqrt(1024)
    for (int p = tid; p < S * S; p += 256) {
        int si = p / S, ti = p - si * S;
        float acc = 0.f;
#pragma unroll
        for (int d = 0; d < DH; d++) acc = fmaf(qs[si][d], ks[ti][d], acc);
        sc[si][ti] = acc * scale;
    }
    __syncthreads();

    if (tid < S) {
        float mx = -1e30f;
        for (int t = 0; t < S; t++) mx = fmaxf(mx, sc[tid][t]);
        float sum = 0.f;
        for (int t = 0; t < S; t++) {
            float e = expf(sc[tid][t] - mx);
            sc[tid][t] = e;
            sum += e;
        }
        float inv = 1.f / sum;
        for (int t = 0; t < S; t++) sc[tid][t] *= inv;
    }
    __syncthreads();

    for (int p = tid; p < S * DH; p += 256) {
        int s = p >> 6;
        int d = p & 63;
        float acc = 0.f;
#pragma unroll
        for (int t = 0; t < S; t++) acc = fmaf(sc[s][t], vs[t][d], acc);
        g_x[(size_t)(s * Bn + b) * Dm + h * DH + d] += acc;   // residual
    }
}

// ---------------------------------------------------------------------------
extern "C" void kernel_launch(void* const* d_in, const int* in_sizes, int n_in,
                              void* d_out, int out_size) {
    const int*   inputs = (const int*)d_in[0];
    // d_in[1] = mask (unused by the reference; DecoderLayer drops it)
    const float* tok = (const float*)d_in[2];
    const float* pe  = (const float*)d_in[3];
    const float* qw  = (const float*)d_in[4];
    const float* qb  = (const float*)d_in[5];
    const float* kw  = (const float*)d_in[6];
    const float* kb  = (const float*)d_in[7];
    const float* vw  = (const float*)d_in[8];
    const float* vb  = (const float*)d_in[9];
    const float* ow  = (const float*)d_in[10];
    const float* ob  = (const float*)d_in[11];
    float* out = (float*)d_out;

    embed_kernel<<<Mr, Dm / 4>>>(inputs, tok, pe);

    for (int l = 0; l < Ln; l++) {
        size_t wOff = (size_t)l * Dm * Dm;
        size_t bOff = (size_t)l * Dm;
        qkv_kernel<<<dim3(Mr / 128, 24), 256>>>(qw + wOff, kw + wOff, vw + wOff,
                                                qb + bOff, kb + bOff, vb + bOff);
        attn_kernel<<<Bn * Hn, 256>>>();
    }

    out_kernel<<<dim3(Mr / 128, Vn / 128), 256>>>(ow, ob, out);
}

// round 3
// speedup vs baseline: 2.9015x; 2.9015x over previous
#include <cuda_runtime.h>
#include <cuda_bf16.h>
#include <cstdint>

constexpr int S  = 24;
constexpr int Bn = 256;
constexpr int Dm = 1024;
constexpr int Ln = 12;
constexpr int Vn = 32000;
constexpr int DH = 64;
constexpr int Mr = S * Bn;          // 6144
constexpr int QKVN = 3 * Dm;        // 3072
constexpr int WROWS = Ln * QKVN;    // 36864

constexpr int BM = 128, BN = 128, BK = 64, STAGES = 3;
constexpr int STAGE_BYTES = (BM * BK + BN * BK) * 2;      // 32 KB
constexpr int SMEM_BYTES  = STAGES * STAGE_BYTES;         // 96 KB
constexpr int NIT = 3 * Dm / BK;                          // 48 (virtual K = 3072)

// ---------------- scratch (device globals; no allocation) ----------------
__device__ float g_x[(size_t)Mr * Dm];
__device__ float g_qkv[(size_t)Mr * QKVN];
__device__ __nv_bfloat16 g_xh[(size_t)Mr * Dm];
__device__ __nv_bfloat16 g_xl[(size_t)Mr * Dm];
__device__ __nv_bfloat16 g_wh[(size_t)WROWS * Dm];
__device__ __nv_bfloat16 g_wl[(size_t)WROWS * Dm];
__device__ __nv_bfloat16 g_owh[(size_t)Vn * Dm];
__device__ __nv_bfloat16 g_owl[(size_t)Vn * Dm];

__device__ __forceinline__ uint32_t smem_u32(const void* p) {
    uint32_t a;
    asm("{ .reg .u64 t; cvta.to.shared.u64 t, %1; cvt.u32.u64 %0, t; }" : "=r"(a) : "l"(p));
    return a;
}

__device__ __forceinline__ void split1(float v, __nv_bfloat16& h, __nv_bfloat16& l) {
    h = __float2bfloat16(v);
    l = __float2bfloat16(v - __bfloat162float(h));
}

// xor swizzle for 128-byte rows (BK=64 bf16): 16B chunk index xored with row%8
__device__ __forceinline__ uint32_t swz(int row, int g) {
    return (uint32_t)(row * 128 + ((g ^ (row & 7)) << 4));
}

// ---------------------------------------------------------------------------
// Split-bf16 GEMM tile via mma.sync: C[128,128] = A[128,1024] . W[128,1024]^T
// Virtual K = 3072: seg0 Ah.Wh, seg1 Ah.Wl, seg2 Al.Wh (fp32 accumulate).
// 256 threads, 8 warps (4 m x 2 n), warp tile 32x64, cp.async 3-stage.
// ---------------------------------------------------------------------------
__device__ __forceinline__ void gemm_tc(
    const __nv_bfloat16* __restrict__ Ah, const __nv_bfloat16* __restrict__ Al,
    const __nv_bfloat16* __restrict__ Wh, const __nv_bfloat16* __restrict__ Wl,
    const float* __restrict__ bias, float* __restrict__ C, int ldC)
{
    extern __shared__ char smem[];
    const uint32_t sb = smem_u32(smem);
    const int tid = threadIdx.x;
    const int lane = tid & 31;
    const int wid = tid >> 5;
    const int wm = wid & 3;         // warp m index (0..3) -> rows 32*wm
    const int wn = wid >> 2;        // warp n index (0..1) -> cols 64*wn

    auto loadStage = [&](int it, int slot) {
        const int seg = it >> 4;                 // 0,1,2
        const int k0  = (it & 15) * BK;
        const __nv_bfloat16* A = (seg < 2) ? Ah : Al;
        const __nv_bfloat16* W = (seg == 1) ? Wl : Wh;
        const uint32_t sa = sb + slot * STAGE_BYTES;
        const uint32_t sw = sa + BM * BK * 2;
#pragma unroll
        for (int i = 0; i < 4; i++) {
            int ch = tid + i * 256;
            int r = ch >> 3, cb = ch & 7;
            const void* gp = A + (size_t)r * Dm + k0 + cb * 8;
            asm volatile("cp.async.cg.shared.global [%0], [%1], 16;"
                         :: "r"(sa + swz(r, cb)), "l"(gp));
        }
#pragma unroll
        for (int i = 0; i < 4; i++) {
            int ch = tid + i * 256;
            int r = ch >> 3, cb = ch & 7;
            const void* gp = W + (size_t)r * Dm + k0 + cb * 8;
            asm volatile("cp.async.cg.shared.global [%0], [%1], 16;"
                         :: "r"(sw + swz(r, cb)), "l"(gp));
        }
        asm volatile("cp.async.commit_group;");
    };

    float acc[2][8][4];
#pragma unroll
    for (int a = 0; a < 2; a++)
#pragma unroll
        for (int b = 0; b < 8; b++)
#pragma unroll
            for (int c = 0; c < 4; c++) acc[a][b][c] = 0.f;

    loadStage(0, 0);
    loadStage(1, 1);

    for (int it = 0; it < NIT; it++) {
        asm volatile("cp.async.wait_group %0;" :: "n"(STAGES - 2));
        __syncthreads();
        if (it + STAGES - 1 < NIT) loadStage(it + STAGES - 1, (it + STAGES - 1) % STAGES);

        const uint32_t sa = sb + (it % STAGES) * STAGE_BYTES;
        const uint32_t sw = sa + BM * BK * 2;
#pragma unroll
        for (int q = 0; q < 4; q++) {           // k16 steps within BK=64
            uint32_t afr[2][4], bfr[8][2];
#pragma unroll
            for (int mi = 0; mi < 2; mi++) {
                int m = wm * 32 + mi * 16 + (lane & 15);
                int g = 2 * q + (lane >> 4);
                asm volatile("ldmatrix.sync.aligned.m8n8.x4.shared.b16 {%0,%1,%2,%3}, [%4];"
                             : "=r"(afr[mi][0]), "=r"(afr[mi][1]),
                               "=r"(afr[mi][2]), "=r"(afr[mi][3])
                             : "r"(sa + swz(m, g)));
            }
#pragma unroll
            for (int nj = 0; nj < 8; nj += 2) {
                int n = wn * 64 + nj * 8 + (lane & 7) + ((lane & 16) >> 1);
                int g = 2 * q + ((lane >> 3) & 1);
                asm volatile("ldmatrix.sync.aligned.m8n8.x4.shared.b16 {%0,%1,%2,%3}, [%4];"
                             : "=r"(bfr[nj][0]), "=r"(bfr[nj][1]),
                               "=r"(bfr[nj + 1][0]), "=r"(bfr[nj + 1][1])
                             : "r"(sw + swz(n, g)));
            }
#pragma unroll
            for (int mi = 0; mi < 2; mi++)
#pragma unroll
                for (int nj = 0; nj < 8; nj++) {
                    asm volatile(
                        "mma.sync.aligned.m16n8k16.row.col.f32.bf16.bf16.f32 "
                        "{%0,%1,%2,%3}, {%4,%5,%6,%7}, {%8,%9}, {%0,%1,%2,%3};"
                        : "+f"(acc[mi][nj][0]), "+f"(acc[mi][nj][1]),
                          "+f"(acc[mi][nj][2]), "+f"(acc[mi][nj][3])
                        : "r"(afr[mi][0]), "r"(afr[mi][1]),
                          "r"(afr[mi][2]), "r"(afr[mi][3]),
                          "r"(bfr[nj][0]), "r"(bfr[nj][1]));
                }
        }
        __syncthreads();
    }

    // epilogue: c0,c1 = (row, col..col+1), c2,c3 = (row+8, ...)
    const int r0 = wm * 32 + (lane >> 2);
    const int cl = 2 * (lane & 3);
#pragma unroll
    for (int mi = 0; mi < 2; mi++)
#pragma unroll
        for (int ro = 0; ro < 2; ro++) {
            int row = r0 + mi * 16 + ro * 8;
            float* crow = C + (size_t)row * ldC;
#pragma unroll
            for (int nj = 0; nj < 8; nj++) {
                int col = wn * 64 + nj * 8 + cl;
                float2 o;
                o.x = acc[mi][nj][ro * 2 + 0] + bias[col];
                o.y = acc[mi][nj][ro * 2 + 1] + bias[col + 1];
                *reinterpret_cast<float2*>(crow + col) = o;
            }
        }
}

// QKV projection: grid (48, 24)
__global__ void __launch_bounds__(256, 2) gemm_qkv_tc(
    int layer, const float* __restrict__ qb, const float* __restrict__ kb,
    const float* __restrict__ vb)
{
    const int mT = blockIdx.x, nT = blockIdx.y;
    const size_t aOff = (size_t)mT * 128 * Dm;
    const size_t wOff = (size_t)(layer * QKVN + nT * 128) * Dm;
    const int mat = nT >> 3;
    const float* bias = ((mat == 0) ? qb : (mat == 1) ? kb : vb)
                        + (size_t)layer * Dm + (nT & 7) * 128 - 0;
    // bias must be indexable by local col (0..127): rebase
    bias -= 0;
    float* C = g_qkv + (size_t)mT * 128 * QKVN + nT * 128;
    gemm_tc(g_xh + aOff, g_xl + aOff, g_wh + wOff, g_wl + wOff, bias, C, QKVN);
}

// Final logits: grid (48, 250)
__global__ void __launch_bounds__(256, 2) gemm_out_tc(
    const float* __restrict__ ob, float* __restrict__ out)
{
    const int mT = blockIdx.x, nT = blockIdx.y;
    const size_t aOff = (size_t)mT * 128 * Dm;
    const size_t wOff = (size_t)nT * 128 * Dm;
    float* C = out + (size_t)mT * 128 * Vn + nT * 128;
    gemm_tc(g_xh + aOff, g_xl + aOff, g_owh + wOff, g_owl + wOff,
            ob + nT * 128, C, Vn);
}

// ---------------------------------------------------------------------------
// Weight splits (fp32 -> bf16 hi/lo)
// ---------------------------------------------------------------------------
__global__ void split_wqkv(const float* __restrict__ qw, const float* __restrict__ kw,
                           const float* __restrict__ vw) {
    size_t t = (size_t)blockIdx.x * 256 + threadIdx.x;
    size_t e = t * 4;
    int row = (int)(e >> 10);
    int col = (int)(e & 1023);
    int l   = row / 3072;
    int rem = row - l * 3072;
    int mat = rem >> 10;
    int n   = rem & 1023;
    const float* src = ((mat == 0) ? qw : (mat == 1) ? kw : vw)
                       + (((size_t)l * 1024 + n) << 10) + col;
    float4 v = *reinterpret_cast<const float4*>(src);
    __nv_bfloat16 h0, h1, h2, h3, l0, l1, l2, l3;
    split1(v.x, h0, l0); split1(v.y, h1, l1); split1(v.z, h2, l2); split1(v.w, h3, l3);
    size_t d = ((size_t)row << 10) + col;
    *reinterpret_cast<__nv_bfloat162*>(g_wh + d)     = __nv_bfloat162(h0, h1);
    *reinterpret_cast<__nv_bfloat162*>(g_wh + d + 2) = __nv_bfloat162(h2, h3);
    *reinterpret_cast<__nv_bfloat162*>(g_wl + d)     = __nv_bfloat162(l0, l1);
    *reinterpret_cast<__nv_bfloat162*>(g_wl + d + 2) = __nv_bfloat162(l2, l3);
}

__global__ void split_wout(const float* __restrict__ ow) {
    size_t t = (size_t)blockIdx.x * 256 + threadIdx.x;
    size_t e = t * 4;
    float4 v = *reinterpret_cast<const float4*>(ow + e);
    __nv_bfloat16 h0, h1, h2, h3, l0, l1, l2, l3;
    split1(v.x, h0, l0); split1(v.y, h1, l1); split1(v.z, h2, l2); split1(v.w, h3, l3);
    *reinterpret_cast<__nv_bfloat162*>(g_owh + e)     = __nv_bfloat162(h0, h1);
    *reinterpret_cast<__nv_bfloat162*>(g_owh + e + 2) = __nv_bfloat162(h2, h3);
    *reinterpret_cast<__nv_bfloat162*>(g_owl + e)     = __nv_bfloat162(l0, l1);
    *reinterpret_cast<__nv_bfloat162*>(g_owl + e + 2) = __nv_bfloat162(l2, l3);
}

// ---------------------------------------------------------------------------
// Embedding + split
// ---------------------------------------------------------------------------
__global__ void embed_kernel(const int* __restrict__ inputs,
                             const float* __restrict__ tok,
                             const float* __restrict__ pe) {
    int row = blockIdx.x;          // s*B + b
    int s = row / Bn;
    int t = inputs[row];
    const float4* te = reinterpret_cast<const float4*>(tok + (size_t)t * Dm);
    const float4* pp = reinterpret_cast<const float4*>(pe + (size_t)s * Dm);
    float4 a = te[threadIdx.x];
    float4 b = pp[threadIdx.x];
    float4 o = make_float4(a.x + b.x, a.y + b.y, a.z + b.z, a.w + b.w);
    size_t d = (size_t)row * Dm + threadIdx.x * 4;
    *reinterpret_cast<float4*>(g_x + d) = o;
    __nv_bfloat16 h0, h1, h2, h3, l0, l1, l2, l3;
    split1(o.x, h0, l0); split1(o.y, h1, l1); split1(o.z, h2, l2); split1(o.w, h3, l3);
    *reinterpret_cast<__nv_bfloat162*>(g_xh + d)     = __nv_bfloat162(h0, h1);
    *reinterpret_cast<__nv_bfloat162*>(g_xh + d + 2) = __nv_bfloat162(h2, h3);
    *reinterpret_cast<__nv_bfloat162*>(g_xl + d)     = __nv_bfloat162(l0, l1);
    *reinterpret_cast<__nv_bfloat162*>(g_xl + d + 2) = __nv_bfloat162(l2, l3);
}

// ---------------------------------------------------------------------------
// Attention per (b,h): scores->softmax->AV->residual + hi/lo split of new x
// ---------------------------------------------------------------------------
__global__ void __launch_bounds__(256) attn_kernel() {
    int bh = blockIdx.x;
    int b = bh >> 4;
    int h = bh & 15;
    __shared__ float qs[S][DH + 1];
    __shared__ float ks[S][DH + 1];
    __shared__ float vs[S][DH + 1];
    __shared__ float sc[S][S];
    int tid = threadIdx.x;

    for (int p = tid; p < S * DH; p += 256) {
        int s = p >> 6, d = p & 63;
        size_t g = (size_t)(s * Bn + b) * QKVN + h * DH + d;
        qs[s][d] = g_qkv[g];
        ks[s][d] = g_qkv[g + 1024];
        vs[s][d] = g_qkv[g + 2048];
    }
    __syncthreads();

    constexpr float scale = 0.03125f;   // 1/sqrt(1024)
    for (int p = tid; p < S * S; p += 256) {
        int si = p / S, ti = p - si * S;
        float acc = 0.f;
#pragma unroll
        for (int d = 0; d < DH; d++) acc = fmaf(qs[si][d], ks[ti][d], acc);
        sc[si][ti] = acc * scale;
    }
    __syncthreads();

    if (tid < S) {
        float mx = -1e30f;
        for (int t = 0; t < S; t++) mx = fmaxf(mx, sc[tid][t]);
        float sum = 0.f;
        for (int t = 0; t < S; t++) {
            float e = expf(sc[tid][t] - mx);
            sc[tid][t] = e;
            sum += e;
        }
        float inv = 1.f / sum;
        for (int t = 0; t < S; t++) sc[tid][t] *= inv;
    }
    __syncthreads();

    for (int p = tid; p < S * DH; p += 256) {
        int s = p >> 6, d = p & 63;
        float acc = 0.f;
#pragma unroll
        for (int t = 0; t < S; t++) acc = fmaf(sc[s][t], vs[t][d], acc);
        size_t xi = (size_t)(s * Bn + b) * Dm + h * DH + d;
        float nv = g_x[xi] + acc;
        g_x[xi] = nv;
        __nv_bfloat16 hh, ll;
        split1(nv, hh, ll);
        g_xh[xi] = hh;
        g_xl[xi] = ll;
    }
}

// ---------------------------------------------------------------------------
extern "C" void kernel_launch(void* const* d_in, const int* in_sizes, int n_in,
                              void* d_out, int out_size) {
    const int*   inputs = (const int*)d_in[0];
    // d_in[1] = mask (reference drops it)
    const float* tok = (const float*)d_in[2];
    const float* pe  = (const float*)d_in[3];
    const float* qw  = (const float*)d_in[4];
    const float* qb  = (const float*)d_in[5];
    const float* kw  = (const float*)d_in[6];
    const float* kb  = (const float*)d_in[7];
    const float* vw  = (const float*)d_in[8];
    const float* vb  = (const float*)d_in[9];
    const float* ow  = (const float*)d_in[10];
    const float* ob  = (const float*)d_in[11];
    float* out = (float*)d_out;

    cudaFuncSetAttribute(gemm_qkv_tc, cudaFuncAttributeMaxDynamicSharedMemorySize, SMEM_BYTES);
    cudaFuncSetAttribute(gemm_out_tc, cudaFuncAttributeMaxDynamicSharedMemorySize, SMEM_BYTES);

    split_wqkv<<<WROWS, 256>>>(qw, kw, vw);
    split_wout<<<Vn, 256>>>(ow);
    embed_kernel<<<Mr, 256>>>(inputs, tok, pe);

    for (int l = 0; l < Ln; l++) {
        gemm_qkv_tc<<<dim3(48, 24), 256, SMEM_BYTES>>>(l, qb, kb, vb);
        attn_kernel<<<Bn * 16, 256>>>();
    }
    gemm_out_tc<<<dim3(48, 250), 256, SMEM_BYTES>>>(ob, out);
}